// round 2
// baseline (speedup 1.0000x reference)
#include <cuda_runtime.h>

#define MAXN 100000
#define HID  128
#define ODIM 400

// Scratch (no cudaMalloc allowed) — device globals.
__device__ float g_deg[MAXN];
__device__ float g_dinv[MAXN];
__device__ float g_sacc[MAXN];
__device__ float g_tacc[MAXN];
__device__ float g_v[HID];

// ---------------------------------------------------------------------------
// 1) init: deg starts at 1.0 (self loops), accumulators at 0
__global__ void k_init(int n) {
    int i = blockIdx.x * blockDim.x + threadIdx.x;
    if (i < n) {
        g_deg[i]  = 1.0f;
        g_sacc[i] = 0.0f;
        g_tacc[i] = 0.0f;
    }
    if (i < HID) g_v[i] = 0.0f;
}

// ---------------------------------------------------------------------------
// 2) degree count over destinations (col). 8 edges/thread for MLP.
__global__ void k_deg(const int* __restrict__ col, int E, int vec_ok) {
    int i = blockIdx.x * blockDim.x + threadIdx.x;
    int e = i * 8;
    if (vec_ok && e + 7 < E) {
        int4 c0 = *reinterpret_cast<const int4*>(col + e);
        int4 c1 = *reinterpret_cast<const int4*>(col + e + 4);
        atomicAdd(&g_deg[c0.x], 1.0f);
        atomicAdd(&g_deg[c0.y], 1.0f);
        atomicAdd(&g_deg[c0.z], 1.0f);
        atomicAdd(&g_deg[c0.w], 1.0f);
        atomicAdd(&g_deg[c1.x], 1.0f);
        atomicAdd(&g_deg[c1.y], 1.0f);
        atomicAdd(&g_deg[c1.z], 1.0f);
        atomicAdd(&g_deg[c1.w], 1.0f);
    } else if (e < E) {
        int lim = min(e + 8, E);
        for (int k = e; k < lim; k++) atomicAdd(&g_deg[col[k]], 1.0f);
    }
}

// ---------------------------------------------------------------------------
// 3) dinv = rsqrt(deg)
__global__ void k_dinv(int n) {
    int i = blockIdx.x * blockDim.x + threadIdx.x;
    if (i < n) g_dinv[i] = rsqrtf(g_deg[i]);
}

// ---------------------------------------------------------------------------
// 4) fused edge pass:
//    sacc[c] += dinv[r] * x[r]      (layer-1 scalar message scatter)
//    tacc[r] += dinv[c]             (layer-2 out-norm accumulation)
__device__ __forceinline__ void edge1(int r, int c, const float* __restrict__ x) {
    float dr = g_dinv[r];
    float dc = g_dinv[c];
    atomicAdd(&g_sacc[c], dr * x[r]);
    atomicAdd(&g_tacc[r], dc);
}

__global__ void k_edge(const int* __restrict__ row, const int* __restrict__ col,
                       const float* __restrict__ x, int E, int vec_ok) {
    int i = blockIdx.x * blockDim.x + threadIdx.x;
    int e = i * 8;
    if (vec_ok && e + 7 < E) {
        int4 r0 = *reinterpret_cast<const int4*>(row + e);
        int4 r1 = *reinterpret_cast<const int4*>(row + e + 4);
        int4 c0 = *reinterpret_cast<const int4*>(col + e);
        int4 c1 = *reinterpret_cast<const int4*>(col + e + 4);
        edge1(r0.x, c0.x, x); edge1(r0.y, c0.y, x);
        edge1(r0.z, c0.z, x); edge1(r0.w, c0.w, x);
        edge1(r1.x, c1.x, x); edge1(r1.y, c1.y, x);
        edge1(r1.z, c1.z, x); edge1(r1.w, c1.w, x);
    } else if (e < E) {
        int lim = min(e + 8, E);
        for (int k = e; k < lim; k++) edge1(row[k], col[k], x);
    }
}

// ---------------------------------------------------------------------------
// 5) v[f] = sum_r t[r] * relu(s[r]*W1[f] + b1[f])
//    s[r] = dinv[r]*sacc[r] + dinv[r]^2 * x[r]   (adds the self-loop term)
//    t[r] = dinv[r]*tacc[r] + dinv[r]^2
//    128 threads/block: thread f owns feature f; nodes broadcast via smem.
__global__ void k_v(const float* __restrict__ x, const float* __restrict__ W1,
                    const float* __restrict__ b1, int n) {
    __shared__ float ssh[128];
    __shared__ float tsh[128];
    int f = threadIdx.x;
    float w  = W1[f];
    float bb = b1[f];
    float acc = 0.0f;

    for (int base = blockIdx.x * 128; base < n; base += gridDim.x * 128) {
        int i = base + f;
        float sv = 0.0f, tv = 0.0f;
        if (i < n) {
            float di = g_dinv[i];
            sv = di * g_sacc[i] + di * di * x[i];
            tv = di * g_tacc[i] + di * di;
        }
        __syncthreads();
        ssh[f] = sv;
        tsh[f] = tv;
        __syncthreads();
        int lim = min(128, n - base);
        #pragma unroll 8
        for (int j = 0; j < lim; j++) {
            float h = fmaxf(fmaf(ssh[j], w, bb), 0.0f);
            acc = fmaf(tsh[j], h, acc);
        }
    }
    atomicAdd(&g_v[f], acc);
}

// ---------------------------------------------------------------------------
// 6) out[o] = (1/N) * sum_f v[f]*W2[f,o] + b2[o]
__global__ void k_out(const float* __restrict__ W2, const float* __restrict__ b2,
                      float* __restrict__ out, int n) {
    __shared__ float vsh[HID];
    if (threadIdx.x < HID) vsh[threadIdx.x] = g_v[threadIdx.x];
    __syncthreads();
    int o = threadIdx.x;
    if (o < ODIM) {
        float acc = 0.0f;
        #pragma unroll 16
        for (int f = 0; f < HID; f++)
            acc = fmaf(vsh[f], W2[f * ODIM + o], acc);
        out[o] = acc * (1.0f / (float)n) + b2[o];
    }
}

// ---------------------------------------------------------------------------
extern "C" void kernel_launch(void* const* d_in, const int* in_sizes, int n_in,
                              void* d_out, int out_size) {
    const float* x  = (const float*)d_in[0];   // [N,1]
    const int*   ei = (const int*)d_in[1];     // [2,E] row-major: row then col
    const float* W1 = (const float*)d_in[2];   // [1,128]
    const float* b1 = (const float*)d_in[3];   // [128]
    const float* W2 = (const float*)d_in[4];   // [128,400]
    const float* b2 = (const float*)d_in[5];   // [400]
    float* out = (float*)d_out;                // [400]

    int n = in_sizes[0];
    int E = in_sizes[1] / 2;
    const int* row = ei;
    const int* col = ei + E;
    // int4 fast path is only safe if the col half-array stays 16B aligned
    int vec_ok = ((E & 3) == 0) ? 1 : 0;

    int nb_n = (n + 255) / 256;
    int eth  = (E + 7) / 8;                    // 8 edges per thread
    int nb_e = (eth + 255) / 256;

    k_init<<<nb_n, 256>>>(n);
    k_deg <<<nb_e, 256>>>(col, E, vec_ok);
    k_dinv<<<nb_n, 256>>>(n);
    k_edge<<<nb_e, 256>>>(row, col, x, E, vec_ok);
    k_v   <<<448, 128>>>(x, W1, b1, n);
    k_out <<<1, 512>>>(W2, b2, out, n);
}

// round 3
// speedup vs baseline: 1.1515x; 1.1515x over previous
#include <cuda_runtime.h>

#define MAXN 100000
#define HID  128
#define ODIM 400

// Scratch (no cudaMalloc allowed) — device globals.
__device__ float g_deg[MAXN];
__device__ float g_dinv[MAXN];
__device__ float g_y[MAXN];     // y[r] = dinv[r] * x[r]  (precomputed gather payload)
__device__ float g_sacc[MAXN];
__device__ float g_tacc[MAXN];
__device__ float g_v[HID];

// ---------------------------------------------------------------------------
// 1) init: deg starts at 1.0 (self loops), accumulators at 0
__global__ void k_init(int n) {
    int i = blockIdx.x * blockDim.x + threadIdx.x;
    if (i < n) {
        g_deg[i]  = 1.0f;
        g_sacc[i] = 0.0f;
        g_tacc[i] = 0.0f;
    }
    if (i < HID) g_v[i] = 0.0f;
}

// ---------------------------------------------------------------------------
// 2) degree count over destinations (col). 8 edges/thread.
__global__ void k_deg(const int* __restrict__ col, int E, int vec_ok) {
    int i = blockIdx.x * blockDim.x + threadIdx.x;
    int e = i * 8;
    if (vec_ok && e + 7 < E) {
        int4 c0 = *reinterpret_cast<const int4*>(col + e);
        int4 c1 = *reinterpret_cast<const int4*>(col + e + 4);
        atomicAdd(&g_deg[c0.x], 1.0f);
        atomicAdd(&g_deg[c0.y], 1.0f);
        atomicAdd(&g_deg[c0.z], 1.0f);
        atomicAdd(&g_deg[c0.w], 1.0f);
        atomicAdd(&g_deg[c1.x], 1.0f);
        atomicAdd(&g_deg[c1.y], 1.0f);
        atomicAdd(&g_deg[c1.z], 1.0f);
        atomicAdd(&g_deg[c1.w], 1.0f);
    } else if (e < E) {
        int lim = min(e + 8, E);
        for (int k = e; k < lim; k++) atomicAdd(&g_deg[col[k]], 1.0f);
    }
}

// ---------------------------------------------------------------------------
// 3) dinv = rsqrt(deg); y = dinv * x   (so k_edge needs only ONE r-side gather)
__global__ void k_dinv(const float* __restrict__ x, int n) {
    int i = blockIdx.x * blockDim.x + threadIdx.x;
    if (i < n) {
        float di = rsqrtf(g_deg[i]);
        g_dinv[i] = di;
        g_y[i]    = di * x[i];
    }
}

// ---------------------------------------------------------------------------
// 4) fused edge pass (4 random L2 sectors per edge):
//    sacc[c] += y[r]        (layer-1 scalar message scatter)
//    tacc[r] += dinv[c]     (layer-2 out-norm accumulation)
__device__ __forceinline__ void edge1(int r, int c) {
    float yr = g_y[r];
    float dc = g_dinv[c];
    atomicAdd(&g_sacc[c], yr);
    atomicAdd(&g_tacc[r], dc);
}

__global__ void k_edge(const int* __restrict__ row, const int* __restrict__ col,
                       int E, int vec_ok) {
    int i = blockIdx.x * blockDim.x + threadIdx.x;
    int e = i * 8;
    if (vec_ok && e + 7 < E) {
        int4 r0 = *reinterpret_cast<const int4*>(row + e);
        int4 r1 = *reinterpret_cast<const int4*>(row + e + 4);
        int4 c0 = *reinterpret_cast<const int4*>(col + e);
        int4 c1 = *reinterpret_cast<const int4*>(col + e + 4);
        edge1(r0.x, c0.x); edge1(r0.y, c0.y);
        edge1(r0.z, c0.z); edge1(r0.w, c0.w);
        edge1(r1.x, c1.x); edge1(r1.y, c1.y);
        edge1(r1.z, c1.z); edge1(r1.w, c1.w);
    } else if (e < E) {
        int lim = min(e + 8, E);
        for (int k = e; k < lim; k++) edge1(row[k], col[k]);
    }
}

// ---------------------------------------------------------------------------
// 5) v[f] = sum_r t[r] * relu(s[r]*W1[f] + b1[f])
//    s[r] = dinv[r]*sacc[r] + dinv[r]*y[r]      (y = dinv*x, so dinv*y = dinv^2*x)
//    t[r] = dinv[r]*tacc[r] + dinv[r]^2
//    128 threads/block: thread f owns feature f; nodes broadcast via smem.
__global__ void k_v(const float* __restrict__ W1, const float* __restrict__ b1,
                    int n) {
    __shared__ float ssh[128];
    __shared__ float tsh[128];
    int f = threadIdx.x;
    float w  = W1[f];
    float bb = b1[f];
    float acc = 0.0f;

    for (int base = blockIdx.x * 128; base < n; base += gridDim.x * 128) {
        int i = base + f;
        float sv = 0.0f, tv = 0.0f;
        if (i < n) {
            float di = g_dinv[i];
            sv = di * (g_sacc[i] + g_y[i]);
            tv = di * (g_tacc[i] + di);
        }
        __syncthreads();
        ssh[f] = sv;
        tsh[f] = tv;
        __syncthreads();
        int lim = min(128, n - base);
        #pragma unroll 8
        for (int j = 0; j < lim; j++) {
            float h = fmaxf(fmaf(ssh[j], w, bb), 0.0f);
            acc = fmaf(tsh[j], h, acc);
        }
    }
    atomicAdd(&g_v[f], acc);
}

// ---------------------------------------------------------------------------
// 6) out[o] = (1/N) * sum_f v[f]*W2[f,o] + b2[o]
__global__ void k_out(const float* __restrict__ W2, const float* __restrict__ b2,
                      float* __restrict__ out, int n) {
    __shared__ float vsh[HID];
    if (threadIdx.x < HID) vsh[threadIdx.x] = g_v[threadIdx.x];
    __syncthreads();
    int o = threadIdx.x;
    if (o < ODIM) {
        float acc = 0.0f;
        #pragma unroll 16
        for (int f = 0; f < HID; f++)
            acc = fmaf(vsh[f], W2[f * ODIM + o], acc);
        out[o] = acc * (1.0f / (float)n) + b2[o];
    }
}

// ---------------------------------------------------------------------------
extern "C" void kernel_launch(void* const* d_in, const int* in_sizes, int n_in,
                              void* d_out, int out_size) {
    const float* x  = (const float*)d_in[0];   // [N,1]
    const int*   ei = (const int*)d_in[1];     // [2,E] row-major: row then col
    const float* W1 = (const float*)d_in[2];   // [1,128]
    const float* b1 = (const float*)d_in[3];   // [128]
    const float* W2 = (const float*)d_in[4];   // [128,400]
    const float* b2 = (const float*)d_in[5];   // [400]
    float* out = (float*)d_out;                // [400]

    int n = in_sizes[0];
    int E = in_sizes[1] / 2;
    const int* row = ei;
    const int* col = ei + E;
    // int4 fast path is only safe if the col half-array stays 16B aligned
    int vec_ok = ((E & 3) == 0) ? 1 : 0;

    int nb_n = (n + 255) / 256;
    int eth  = (E + 7) / 8;                    // 8 edges per thread
    int nb_e = (eth + 255) / 256;

    k_init<<<nb_n, 256>>>(n);
    k_deg <<<nb_e, 256>>>(col, E, vec_ok);
    k_dinv<<<nb_n, 256>>>(x, n);
    k_edge<<<nb_e, 256>>>(row, col, E, vec_ok);
    k_v   <<<448, 128>>>(W1, b1, n);
    k_out <<<1, 512>>>(W2, b2, out, n);
}